// round 7
// baseline (speedup 1.0000x reference)
#include <cuda_runtime.h>
#include <cstdint>
#include <cstddef>

// Problem constants
#define Bb 64
#define Nt 577
#define Cc 768
#define Hh 12
#define SCv 0.125f
#define SPLITS 9
#define CHUNK 66        // 9*66=594 >= 577, divisible by G
#define G 6             // tokens per group in k_attn2
#define NPAD 608        // padded token count (zero weights beyond 577)

// ---------------- scratch (device globals; zero-initialized, no allocation) ----------------
__device__ __align__(16) float g_qpart[12][Bb][Cc];            // q partial sums (kc,b,j)
__device__ __align__(16) float g_t[Bb][Hh][Cc];                // SCALE * (q . Wk)
__device__ float            g_ob[Bb][Hh];                      // SCALE * (q . bk)
__device__ __align__(16) float g_lg[Bb][Hh][NPAD];             // logits
__device__ __align__(16) unsigned long long g_w2[Bb][NPAD][12];// normalized weights, dup-packed
__device__ __align__(16) float g_pu[SPLITS][Bb][Hh][Cc];       // partial sum_n w*x
__device__ __align__(16) float g_ubar[Bb][Hh][Cc];             // combined u (already normalized)
__device__ __align__(16) float g_clsp[12][Bb][Cc];             // cls partials
__device__ __align__(16) float g_outp[12][Bb][Cc];             // proj partials

// ---------------- helpers ----------------
typedef unsigned long long ull;
__device__ __forceinline__ void fma2(ull &d, ull a, ull b) {
    asm("fma.rn.f32x2 %0, %1, %2, %0;" : "+l"(d) : "l"(a), "l"(b));
}
__device__ __forceinline__ ull dup2(float v) {
    ull r;
    asm("mov.b64 %0, {%1,%1};" : "=l"(r) : "r"(__float_as_uint(v)));
    return r;
}
__device__ __forceinline__ void cpa16(void* dst_smem, const void* src) {
    unsigned int d = (unsigned int)__cvta_generic_to_shared(dst_smem);
    asm volatile("cp.async.cg.shared.global [%0], [%1], 16;" :: "r"(d), "l"(src));
}

// ---------------- A1: q partials (k-split GEMM) ----------------
__global__ void k_qpart(const float* __restrict__ x, const float* __restrict__ qkv_w) {
    int jc = blockIdx.x, kc = blockIdx.y;
    __shared__ float xs[64][65];
    __shared__ float ws[64][65];
    int tid = threadIdx.x;
    for (int i = tid; i < 64 * 16; i += 256) {
        int r = i >> 4, c4 = (i & 15) * 4;
        float4 xv = *(const float4*)&x[(size_t)r * Nt * Cc + kc * 64 + c4];
        xs[r][c4] = xv.x; xs[r][c4 + 1] = xv.y; xs[r][c4 + 2] = xv.z; xs[r][c4 + 3] = xv.w;
        float4 wv = *(const float4*)&qkv_w[(size_t)(jc * 64 + r) * Cc + kc * 64 + c4];
        ws[r][c4] = wv.x; ws[r][c4 + 1] = wv.y; ws[r][c4 + 2] = wv.z; ws[r][c4 + 3] = wv.w;
    }
    __syncthreads();
    int ty = tid >> 4, tx = tid & 15;
    float acc[4][4] = {};
#pragma unroll 8
    for (int d = 0; d < 64; d++) {
        float a0 = xs[ty * 4 + 0][d], a1 = xs[ty * 4 + 1][d];
        float a2 = xs[ty * 4 + 2][d], a3 = xs[ty * 4 + 3][d];
        float b0 = ws[tx * 4 + 0][d], b1 = ws[tx * 4 + 1][d];
        float b2 = ws[tx * 4 + 2][d], b3 = ws[tx * 4 + 3][d];
        acc[0][0] += a0 * b0; acc[0][1] += a0 * b1; acc[0][2] += a0 * b2; acc[0][3] += a0 * b3;
        acc[1][0] += a1 * b0; acc[1][1] += a1 * b1; acc[1][2] += a1 * b2; acc[1][3] += a1 * b3;
        acc[2][0] += a2 * b0; acc[2][1] += a2 * b1; acc[2][2] += a2 * b2; acc[2][3] += a2 * b3;
        acc[3][0] += a3 * b0; acc[3][1] += a3 * b1; acc[3][2] += a3 * b2; acc[3][3] += a3 * b3;
    }
#pragma unroll
    for (int i = 0; i < 4; i++) {
        float4 v = make_float4(acc[i][0], acc[i][1], acc[i][2], acc[i][3]);
        *(float4*)&g_qpart[kc][ty * 4 + i][jc * 64 + tx * 4] = v;
    }
}

// ---------------- A2: t = SCALE*(q.Wk); ob  (q combined in-block) ----------------
__global__ void k_t(const float* __restrict__ qkv_w, const float* __restrict__ qkv_b) {
    int h = blockIdx.x, cc2 = blockIdx.y;
    __shared__ float qs[64][65];
    __shared__ float wk[64][65];
    int tid = threadIdx.x;
    for (int i = tid; i < 64 * 16; i += 256) {
        int r = i >> 4, c4 = (i & 15) * 4;
        float4 s = *(const float4*)&qkv_b[h * 64 + c4];
#pragma unroll
        for (int kc = 0; kc < 12; kc++) {
            float4 p = *(const float4*)&g_qpart[kc][r][h * 64 + c4];
            s.x += p.x; s.y += p.y; s.z += p.z; s.w += p.w;
        }
        qs[r][c4] = s.x; qs[r][c4 + 1] = s.y; qs[r][c4 + 2] = s.z; qs[r][c4 + 3] = s.w;
        float4 wv = *(const float4*)&qkv_w[(size_t)(Cc + h * 64 + r) * Cc + cc2 * 64 + c4];
        wk[r][c4] = wv.x; wk[r][c4 + 1] = wv.y; wk[r][c4 + 2] = wv.z; wk[r][c4 + 3] = wv.w;
    }
    __syncthreads();
    int ty = tid >> 4, tx = tid & 15;
    float acc[4][4] = {};
#pragma unroll 8
    for (int d = 0; d < 64; d++) {
        float a0 = qs[ty * 4 + 0][d], a1 = qs[ty * 4 + 1][d];
        float a2 = qs[ty * 4 + 2][d], a3 = qs[ty * 4 + 3][d];
        float b0 = wk[d][tx * 4 + 0], b1 = wk[d][tx * 4 + 1];
        float b2 = wk[d][tx * 4 + 2], b3 = wk[d][tx * 4 + 3];
        acc[0][0] += a0 * b0; acc[0][1] += a0 * b1; acc[0][2] += a0 * b2; acc[0][3] += a0 * b3;
        acc[1][0] += a1 * b0; acc[1][1] += a1 * b1; acc[1][2] += a1 * b2; acc[1][3] += a1 * b3;
        acc[2][0] += a2 * b0; acc[2][1] += a2 * b1; acc[2][2] += a2 * b2; acc[2][3] += a2 * b3;
        acc[3][0] += a3 * b0; acc[3][1] += a3 * b1; acc[3][2] += a3 * b2; acc[3][3] += a3 * b3;
    }
#pragma unroll
    for (int i = 0; i < 4; i++) {
        float4 v = make_float4(SCv * acc[i][0], SCv * acc[i][1], SCv * acc[i][2], SCv * acc[i][3]);
        *(float4*)&g_t[ty * 4 + i][h][cc2 * 64 + tx * 4] = v;
    }
    if (cc2 == 0 && tid < 64) {
        float ssum = 0.f;
#pragma unroll 8
        for (int d = 0; d < 64; d++) ssum += qs[tid][d] * qkv_b[Cc + h * 64 + d];
        g_ob[tid][h] = SCv * ssum;
    }
}

// ---------------- L: logits GEMM: g_lg[b][h][n] = x[b,n,:].t[b,h,:] ----------------
// grid (10 ntile, 64 b), 256 thr: thread = (token, head-triple)
__global__ void k_logit(const float* __restrict__ x) {
    int nt = blockIdx.x, b = blockIdx.y;
    int n0 = nt * 64;
    __shared__ float xs[64][68];
    __shared__ float ts[12][68];
    int tid = threadIdx.x;
    int tok = tid >> 2, g3 = tid & 3;
    int h0 = g3 * 3;
    float acc0 = 0.f, acc1 = 0.f, acc2 = 0.f;

    for (int kc = 0; kc < 12; kc++) {
        __syncthreads();          // protect previous chunk's smem
        // load x tile: 64 tokens x 64 ch = 1024 float4
#pragma unroll
        for (int r = 0; r < 4; r++) {
            int idx = tid + r * 256;
            int row = idx >> 4, c4 = (idx & 15) * 4;
            int n = n0 + row; int nsrc = n < Nt ? n : Nt - 1;
            cpa16(&xs[row][c4], &x[((size_t)b * Nt + nsrc) * Cc + kc * 64 + c4]);
        }
        // load t tile: 12 heads x 64 ch = 192 float4
        if (tid < 192) {
            int row = tid >> 4, c4 = (tid & 15) * 4;
            cpa16(&ts[row][c4], &g_t[b][row][kc * 64 + c4]);
        }
        asm volatile("cp.async.commit_group;");
        asm volatile("cp.async.wait_group 0;");
        __syncthreads();
#pragma unroll
        for (int c4 = 0; c4 < 64; c4 += 4) {
            float4 xv = *(const float4*)&xs[tok][c4];
            float4 t0 = *(const float4*)&ts[h0 + 0][c4];
            float4 t1 = *(const float4*)&ts[h0 + 1][c4];
            float4 t2 = *(const float4*)&ts[h0 + 2][c4];
            acc0 += xv.x * t0.x + xv.y * t0.y + xv.z * t0.z + xv.w * t0.w;
            acc1 += xv.x * t1.x + xv.y * t1.y + xv.z * t1.z + xv.w * t1.w;
            acc2 += xv.x * t2.x + xv.y * t2.y + xv.z * t2.z + xv.w * t2.w;
        }
    }
    int n = n0 + tok;
    if (n < Nt) {
        g_lg[b][h0 + 0][n] = acc0;
        g_lg[b][h0 + 1][n] = acc1;
        g_lg[b][h0 + 2][n] = acc2;
    }
}

// ---------------- S: softmax per (b,h): normalized dup-packed weights ----------------
// grid 64, 384 thr (warp = head)
__global__ void k_soft(void) {
    int b = blockIdx.x;
    int tid = threadIdx.x;
    int h = tid >> 5, l = tid & 31;
    float ob = g_ob[b][h];
    float e[19];
    float sum = 0.f;
#pragma unroll
    for (int i = 0; i < 19; i++) {
        int n = i * 32 + l;
        float wv = 0.f;
        if (n < Nt) wv = __expf(g_lg[b][h][n] + ob);   // logits tiny; no max needed
        e[i] = wv;
        sum += wv;
    }
#pragma unroll
    for (int off = 16; off; off >>= 1) sum += __shfl_xor_sync(0xffffffffu, sum, off);
    float inv = 1.f / sum;
#pragma unroll
    for (int i = 0; i < 19; i++) {
        int n = i * 32 + l;
        if (n < Nt) g_w2[b][n][h] = dup2(e[i] * inv);
    }
}

// ---------------- B: streaming accumulate + copy ----------------
// grid (64 b, 9 split), 384 thr; lane owns 2 channels (c2 = tid*2)
__global__ void __launch_bounds__(384) k_attn2(const float* __restrict__ x,
                                               float* __restrict__ out) {
    int b = blockIdx.x, sp = blockIdx.y;
    int n0 = sp * CHUNK;
    int tid = threadIdx.x;
    int c2 = tid * 2;

    __shared__ __align__(16) float xb[2][G][Cc];
    __shared__ __align__(16) ull  wsb[2][G][12];

    ull ua[12];
#pragma unroll
    for (int h = 0; h < 12; h++) ua[h] = 0ull;

    const float* xrow = x + (size_t)b * Nt * Cc;

    // prologue: group 0
#pragma unroll
    for (int r = 0; r < 3; r++) {
        int idx = tid + r * 384;
        int j = idx / 192, off = (idx % 192) * 4;
        int n = n0 + j; int nsrc = n < Nt ? n : Nt - 1;
        cpa16(&xb[0][j][off], xrow + (size_t)nsrc * Cc + off);
    }
    if (tid < 36)
        cpa16((char*)&wsb[0][0][0] + tid * 16, (const char*)&g_w2[b][n0][0] + tid * 16);
    asm volatile("cp.async.commit_group;");

    const int NG = CHUNK / G;   // 11
    for (int gi = 0; gi < NG; gi++) {
        int buf = gi & 1;
        int nbase = n0 + gi * G;
        // prefetch group gi+1 into buf^1
        if (gi + 1 < NG) {
            int nb2 = nbase + G;
#pragma unroll
            for (int r = 0; r < 3; r++) {
                int idx = tid + r * 384;
                int j = idx / 192, off = (idx % 192) * 4;
                int n = nb2 + j; int nsrc = n < Nt ? n : Nt - 1;
                cpa16(&xb[buf ^ 1][j][off], xrow + (size_t)nsrc * Cc + off);
            }
            if (tid < 36)
                cpa16((char*)&wsb[buf ^ 1][0][0] + tid * 16,
                      (const char*)&g_w2[b][nb2][0] + tid * 16);
        }
        asm volatile("cp.async.commit_group;");
        asm volatile("cp.async.wait_group 1;");
        __syncthreads();

#pragma unroll
        for (int j = 0; j < G; j++) {
            int n = nbase + j;
            ull xv = *(const ull*)&xb[buf][j][c2];
#pragma unroll
            for (int h = 0; h < 12; h++)
                fma2(ua[h], wsb[buf][j][h], xv);     // zero weights beyond 577 -> no-op
            if (n > 0 && n < Nt)
                *(ull*)&out[((size_t)b * Nt + n) * Cc + c2] = xv;
        }
        __syncthreads();
    }

    // store split partials (weights already normalized)
#pragma unroll
    for (int h = 0; h < 12; h++)
        *(ull*)&g_pu[sp][b][h][c2] = ua[h];
}

// ---------------- B2: wide sum of u partials ----------------
__global__ void k_ured(void) {
    int idx = blockIdx.x * 256 + threadIdx.x;
    if (idx >= Bb * Hh * Cc / 4) return;
    int c4 = (idx % 192) * 4;
    int h = (idx / 192) % Hh;
    int b = idx / (192 * Hh);
    float4 acc = make_float4(0.f, 0.f, 0.f, 0.f);
#pragma unroll
    for (int s = 0; s < SPLITS; s++) {
        float4 p = *(const float4*)&g_pu[s][b][h][c4];
        acc.x += p.x; acc.y += p.y; acc.z += p.z; acc.w += p.w;
    }
    *(float4*)&g_ubar[b][h][c4] = acc;
}

// ---------------- C1: cls partials ----------------
__global__ void k_cls(const float* __restrict__ qkv_w) {
    int h = blockIdx.x, kc = blockIdx.y;
    __shared__ float us[64][65];
    __shared__ float wv[64][65];
    int tid = threadIdx.x;
    for (int i = tid; i < 64 * 16; i += 256) {
        int r = i >> 4, c4 = (i & 15) * 4;
        float4 uv = *(const float4*)&g_ubar[r][h][kc * 64 + c4];
        us[r][c4] = uv.x; us[r][c4 + 1] = uv.y; us[r][c4 + 2] = uv.z; us[r][c4 + 3] = uv.w;
        float4 wvv = *(const float4*)&qkv_w[(size_t)(2 * Cc + h * 64 + r) * Cc + kc * 64 + c4];
        wv[r][c4] = wvv.x; wv[r][c4 + 1] = wvv.y; wv[r][c4 + 2] = wvv.z; wv[r][c4 + 3] = wvv.w;
    }
    __syncthreads();
    int ty = tid >> 4, tx = tid & 15;
    float acc[4][4] = {};
#pragma unroll 8
    for (int c = 0; c < 64; c++) {
        float a0 = us[ty * 4 + 0][c], a1 = us[ty * 4 + 1][c];
        float a2 = us[ty * 4 + 2][c], a3 = us[ty * 4 + 3][c];
        float b0 = wv[tx * 4 + 0][c], b1 = wv[tx * 4 + 1][c];
        float b2 = wv[tx * 4 + 2][c], b3 = wv[tx * 4 + 3][c];
        acc[0][0] += a0 * b0; acc[0][1] += a0 * b1; acc[0][2] += a0 * b2; acc[0][3] += a0 * b3;
        acc[1][0] += a1 * b0; acc[1][1] += a1 * b1; acc[1][2] += a1 * b2; acc[1][3] += a1 * b3;
        acc[2][0] += a2 * b0; acc[2][1] += a2 * b1; acc[2][2] += a2 * b2; acc[2][3] += a2 * b3;
        acc[3][0] += a3 * b0; acc[3][1] += a3 * b1; acc[3][2] += a3 * b2; acc[3][3] += a3 * b3;
    }
#pragma unroll
    for (int i = 0; i < 4; i++) {
        float4 v = make_float4(acc[i][0], acc[i][1], acc[i][2], acc[i][3]);
        *(float4*)&g_clsp[kc][ty * 4 + i][h * 64 + tx * 4] = v;
    }
}

// ---------------- C2: proj partials ----------------
__global__ void k_proj(const float* __restrict__ qkv_b, const float* __restrict__ proj_w) {
    int jc = blockIdx.x, kc = blockIdx.y;
    __shared__ float cs[64][65];
    __shared__ float pw[64][65];
    int tid = threadIdx.x;
    for (int i = tid; i < 64 * 16; i += 256) {
        int r = i >> 4, c4 = (i & 15) * 4;
        float4 s = *(const float4*)&qkv_b[2 * Cc + kc * 64 + c4];
#pragma unroll
        for (int p = 0; p < 12; p++) {
            float4 pv = *(const float4*)&g_clsp[p][r][kc * 64 + c4];
            s.x += pv.x; s.y += pv.y; s.z += pv.z; s.w += pv.w;
        }
        cs[r][c4] = s.x; cs[r][c4 + 1] = s.y; cs[r][c4 + 2] = s.z; cs[r][c4 + 3] = s.w;
        float4 wv = *(const float4*)&proj_w[(size_t)(jc * 64 + r) * Cc + kc * 64 + c4];
        pw[r][c4] = wv.x; pw[r][c4 + 1] = wv.y; pw[r][c4 + 2] = wv.z; pw[r][c4 + 3] = wv.w;
    }
    __syncthreads();
    int ty = tid >> 4, tx = tid & 15;
    float acc[4][4] = {};
#pragma unroll 8
    for (int c = 0; c < 64; c++) {
        float a0 = cs[ty * 4 + 0][c], a1 = cs[ty * 4 + 1][c];
        float a2 = cs[ty * 4 + 2][c], a3 = cs[ty * 4 + 3][c];
        float b0 = pw[tx * 4 + 0][c], b1 = pw[tx * 4 + 1][c];
        float b2 = pw[tx * 4 + 2][c], b3 = pw[tx * 4 + 3][c];
        acc[0][0] += a0 * b0; acc[0][1] += a0 * b1; acc[0][2] += a0 * b2; acc[0][3] += a0 * b3;
        acc[1][0] += a1 * b0; acc[1][1] += a1 * b1; acc[1][2] += a1 * b2; acc[1][3] += a1 * b3;
        acc[2][0] += a2 * b0; acc[2][1] += a2 * b1; acc[2][2] += a2 * b2; acc[2][3] += a2 * b3;
        acc[3][0] += a3 * b0; acc[3][1] += a3 * b1; acc[3][2] += a3 * b2; acc[3][3] += a3 * b3;
    }
#pragma unroll
    for (int i = 0; i < 4; i++) {
        float4 v = make_float4(acc[i][0], acc[i][1], acc[i][2], acc[i][3]);
        *(float4*)&g_outp[kc][ty * 4 + i][jc * 64 + tx * 4] = v;
    }
}

// ---------------- C3: combine proj partials + proj_b -> out[:,0,:] ----------------
__global__ void k_final(const float* __restrict__ proj_b, float* __restrict__ out) {
    int idx = blockIdx.x * 256 + threadIdx.x;
    if (idx >= Bb * Cc / 4) return;
    int b = idx / 192, j4 = (idx % 192) * 4;
    float4 s = *(const float4*)&proj_b[j4];
#pragma unroll
    for (int p = 0; p < 12; p++) {
        float4 pv = *(const float4*)&g_outp[p][b][j4];
        s.x += pv.x; s.y += pv.y; s.z += pv.z; s.w += pv.w;
    }
    *(float4*)&out[(size_t)b * Nt * Cc + j4] = s;
}

// ---------------- launch ----------------
extern "C" void kernel_launch(void* const* d_in, const int* in_sizes, int n_in,
                              void* d_out, int out_size) {
    (void)in_sizes; (void)n_in; (void)out_size;
    const float* x      = (const float*)d_in[0];
    const float* qkv_w  = (const float*)d_in[1];
    const float* qkv_b  = (const float*)d_in[2];
    const float* proj_w = (const float*)d_in[3];
    const float* proj_b = (const float*)d_in[4];
    float* out = (float*)d_out;

    k_qpart<<<dim3(12, 12), 256>>>(x, qkv_w);
    k_t    <<<dim3(12, 12), 256>>>(qkv_w, qkv_b);
    k_logit<<<dim3(10, 64), 256>>>(x);
    k_soft <<<64, 384>>>();
    k_attn2<<<dim3(64, SPLITS), 384>>>(x, out);
    k_ured <<<576, 256>>>();
    k_cls  <<<dim3(12, 12), 256>>>(qkv_w);
    k_proj <<<dim3(12, 12), 256>>>(qkv_b, proj_w);
    k_final<<<48, 256>>>(proj_b, out);
}

// round 8
// speedup vs baseline: 1.2365x; 1.2365x over previous
#include <cuda_runtime.h>
#include <cstdint>
#include <cstddef>

// Problem constants
#define Bb 64
#define Nt 577
#define Cc 768
#define Hh 12
#define SCv 0.125f
#define SPLITS 9
#define CHUNK 65        // ceil(577/9)
#define G 6             // tokens per group in k_attn

// ---------------- scratch (device globals; no allocation) ----------------
__device__ __align__(16) float g_qpart[12][Bb][Cc];            // q partial sums (kc,b,j)
__device__ __align__(16) float g_t[Bb][Hh][Cc];                // SCALE * (q . Wk)
__device__ float            g_ob[Bb][Hh];                      // SCALE * (q . bk)
__device__ __align__(16) float g_pu[SPLITS][Bb][Hh][Cc];       // partial sum_n w*x
__device__ float            g_pd[SPLITS][Bb][Hh];              // partial sum_n w
__device__ __align__(16) float g_clsp[12][Bb][Cc];             // cls partials
__device__ __align__(16) float g_outp[12][Bb][Cc];             // proj partials

// ---------------- helpers ----------------
typedef unsigned long long ull;
__device__ __forceinline__ void fma2(ull &d, ull a, ull b) {
    asm("fma.rn.f32x2 %0, %1, %2, %0;" : "+l"(d) : "l"(a), "l"(b));
}
__device__ __forceinline__ float hadd2(ull a) {
    unsigned int lo, hi;
    asm("mov.b64 {%0,%1}, %2;" : "=r"(lo), "=r"(hi) : "l"(a));
    return __uint_as_float(lo) + __uint_as_float(hi);
}
__device__ __forceinline__ void cpa16(void* dst_smem, const void* src) {
    unsigned int d = (unsigned int)__cvta_generic_to_shared(dst_smem);
    asm volatile("cp.async.cg.shared.global [%0], [%1], 16;" :: "r"(d), "l"(src));
}
__device__ __forceinline__ void cpa8(float* dst_smem, const float* src) {
    unsigned int d = (unsigned int)__cvta_generic_to_shared(dst_smem);
    asm volatile("cp.async.ca.shared.global [%0], [%1], 8;" :: "r"(d), "l"(src));
}

// ---------------- A1: q partials (k-split GEMM), 512 threads ----------------
__global__ void __launch_bounds__(512) k_qpart(const float* __restrict__ x,
                                               const float* __restrict__ qkv_w) {
    int jc = blockIdx.x, kc = blockIdx.y;
    __shared__ float xs[64][65];
    __shared__ float ws[64][65];
    int tid = threadIdx.x;
#pragma unroll
    for (int rr = 0; rr < 2; rr++) {
        int i = tid + rr * 512;
        int r = i >> 4, c4 = (i & 15) * 4;
        float4 xv = *(const float4*)&x[(size_t)r * Nt * Cc + kc * 64 + c4];
        xs[r][c4] = xv.x; xs[r][c4 + 1] = xv.y; xs[r][c4 + 2] = xv.z; xs[r][c4 + 3] = xv.w;
        float4 wv = *(const float4*)&qkv_w[(size_t)(jc * 64 + r) * Cc + kc * 64 + c4];
        ws[r][c4] = wv.x; ws[r][c4 + 1] = wv.y; ws[r][c4 + 2] = wv.z; ws[r][c4 + 3] = wv.w;
    }
    __syncthreads();
    int ty = tid >> 4, tx = tid & 15;     // 32 x 16
    float acc[2][4] = {};
#pragma unroll 8
    for (int d = 0; d < 64; d++) {
        float a0 = xs[ty * 2 + 0][d], a1 = xs[ty * 2 + 1][d];
        float b0 = ws[tx * 4 + 0][d], b1 = ws[tx * 4 + 1][d];
        float b2 = ws[tx * 4 + 2][d], b3 = ws[tx * 4 + 3][d];
        acc[0][0] += a0 * b0; acc[0][1] += a0 * b1; acc[0][2] += a0 * b2; acc[0][3] += a0 * b3;
        acc[1][0] += a1 * b0; acc[1][1] += a1 * b1; acc[1][2] += a1 * b2; acc[1][3] += a1 * b3;
    }
#pragma unroll
    for (int i = 0; i < 2; i++) {
        float4 v = make_float4(acc[i][0], acc[i][1], acc[i][2], acc[i][3]);
        *(float4*)&g_qpart[kc][ty * 2 + i][jc * 64 + tx * 4] = v;
    }
}

// ---------------- A2: t = SCALE*(q.Wk); ob  (q combined in-block), 512 thr ----------------
__global__ void __launch_bounds__(512) k_t(const float* __restrict__ qkv_w,
                                           const float* __restrict__ qkv_b) {
    int h = blockIdx.x, cc2 = blockIdx.y;
    __shared__ float qs[64][65];
    __shared__ float wk[64][65];
    int tid = threadIdx.x;
#pragma unroll
    for (int rr = 0; rr < 2; rr++) {
        int i = tid + rr * 512;
        int r = i >> 4, c4 = (i & 15) * 4;
        float4 s = *(const float4*)&qkv_b[h * 64 + c4];
#pragma unroll
        for (int kc = 0; kc < 12; kc++) {
            float4 p = *(const float4*)&g_qpart[kc][r][h * 64 + c4];
            s.x += p.x; s.y += p.y; s.z += p.z; s.w += p.w;
        }
        qs[r][c4] = s.x; qs[r][c4 + 1] = s.y; qs[r][c4 + 2] = s.z; qs[r][c4 + 3] = s.w;
        float4 wv = *(const float4*)&qkv_w[(size_t)(Cc + h * 64 + r) * Cc + cc2 * 64 + c4];
        wk[r][c4] = wv.x; wk[r][c4 + 1] = wv.y; wk[r][c4 + 2] = wv.z; wk[r][c4 + 3] = wv.w;
    }
    __syncthreads();
    int ty = tid >> 4, tx = tid & 15;
    float acc[2][4] = {};
#pragma unroll 8
    for (int d = 0; d < 64; d++) {
        float a0 = qs[ty * 2 + 0][d], a1 = qs[ty * 2 + 1][d];
        float b0 = wk[d][tx * 4 + 0], b1 = wk[d][tx * 4 + 1];
        float b2 = wk[d][tx * 4 + 2], b3 = wk[d][tx * 4 + 3];
        acc[0][0] += a0 * b0; acc[0][1] += a0 * b1; acc[0][2] += a0 * b2; acc[0][3] += a0 * b3;
        acc[1][0] += a1 * b0; acc[1][1] += a1 * b1; acc[1][2] += a1 * b2; acc[1][3] += a1 * b3;
    }
#pragma unroll
    for (int i = 0; i < 2; i++) {
        float4 v = make_float4(SCv * acc[i][0], SCv * acc[i][1], SCv * acc[i][2], SCv * acc[i][3]);
        *(float4*)&g_t[ty * 2 + i][h][cc2 * 64 + tx * 4] = v;
    }
    if (cc2 == 0 && tid < 64) {
        float ssum = 0.f;
#pragma unroll 8
        for (int d = 0; d < 64; d++) ssum += qs[tid][d] * qkv_b[Cc + h * 64 + d];
        g_ob[tid][h] = SCv * ssum;
    }
}

// ---------------- B: main fused streaming kernel (PROVEN R3, verbatim) ----------------
// grid (64 b, 9 split), 384 thr.  warp = 64-channel slice.
// Phase 1: lane-groups of 8, 3 heads each, shfl width=8 reductions.
// Phase 2: 2 channels/lane, scalar fmaf with float4 wsm reads.
__global__ void __launch_bounds__(384, 2) k_attn(const float* __restrict__ x,
                                                 float* __restrict__ out) {
    int b = blockIdx.x, sp = blockIdx.y;
    int n0 = sp * CHUNK;
    int n1 = n0 + CHUNK; if (n1 > Nt) n1 = Nt;
    int ng = (n1 - n0 + G - 1) / G;
    int tid = threadIdx.x;
    int w = tid >> 5, l = tid & 31;
    int g3 = l >> 3;           // lane group 0..3 -> heads 3*g3..3*g3+2
    int q = l & 7;             // lane in group

    __shared__ __align__(16) float xb[2][G][Cc];
    __shared__ __align__(16) float pl[G][12][12];   // [token][warp][head]
    __shared__ __align__(16) float wsm[G][16];
    __shared__ float obs[12];
    __shared__ float dsm[G * 12];

    // phase-1 t: heads 3g3..3g3+2, channels w*64 + q*8 .. +7, packed
    int c1 = w * 64 + q * 8;
    ull t1[3][4];
#pragma unroll
    for (int i = 0; i < 3; i++) {
        ulonglong2 p0 = *(const ulonglong2*)&g_t[b][g3 * 3 + i][c1];
        ulonglong2 p1 = *(const ulonglong2*)&g_t[b][g3 * 3 + i][c1 + 4];
        t1[i][0] = p0.x; t1[i][1] = p0.y; t1[i][2] = p1.x; t1[i][3] = p1.y;
    }
    if (tid < 12) obs[tid] = g_ob[b][tid];

    // phase-2 accumulators: 2 channels per lane, all 12 heads
    int c2 = w * 64 + l * 2;
    float2 ua[12];
#pragma unroll
    for (int h = 0; h < 12; h++) ua[h] = make_float2(0.f, 0.f);
    float dp = 0.f;

    const float* xrow = x + (size_t)b * Nt * Cc;
    __syncthreads();

    // prologue: load group 0
#pragma unroll
    for (int r = 0; r < 3; r++) {
        int i = tid + r * 384;
        int j = i / 192, off = (i % 192) * 4;
        int n = n0 + j;
        if (n < n1) cpa16(&xb[0][j][off], xrow + (size_t)n * Cc + off);
    }
    asm volatile("cp.async.commit_group;");

    for (int gi = 0; gi < ng; gi++) {
        int buf = gi & 1;
        int nbase = n0 + gi * G;
        // prefetch next group
        {
            int nb2 = nbase + G;
#pragma unroll
            for (int r = 0; r < 3; r++) {
                int i = tid + r * 384;
                int j = i / 192, off = (i % 192) * 4;
                int n = nb2 + j;
                if (gi + 1 < ng && n < n1) cpa16(&xb[buf ^ 1][j][off], xrow + (size_t)n * Cc + off);
            }
            asm volatile("cp.async.commit_group;");
        }
        asm volatile("cp.async.wait_group 1;");
        __syncthreads();

        // ---- phase 1: logits ----
#pragma unroll
        for (int j = 0; j < G; j++) {
            int n = nbase + j;
            if (n >= n1) break;
            ulonglong2 xp0 = *(const ulonglong2*)&xb[buf][j][c1];
            ulonglong2 xp1 = *(const ulonglong2*)&xb[buf][j][c1 + 4];
            ull xv0 = xp0.x, xv1 = xp0.y, xv2 = xp1.x, xv3 = xp1.y;
            float s[3];
#pragma unroll
            for (int i = 0; i < 3; i++) {
                ull a = 0ull;
                fma2(a, xv0, t1[i][0]); fma2(a, xv1, t1[i][1]);
                fma2(a, xv2, t1[i][2]); fma2(a, xv3, t1[i][3]);
                float sv = hadd2(a);
                sv += __shfl_xor_sync(0xffffffffu, sv, 4, 8);
                sv += __shfl_xor_sync(0xffffffffu, sv, 2, 8);
                sv += __shfl_xor_sync(0xffffffffu, sv, 1, 8);
                s[i] = sv;
            }
            if (q < 3) pl[j][w][g3 * 3 + q] = s[q];
        }
        __syncthreads();

        // ---- combine: 72 threads -> weights ----
        if (tid < G * 12) {
            int gg = tid / 12, h = tid % 12;
            int n = nbase + gg;
            float s = 0.f;
#pragma unroll
            for (int ww = 0; ww < 12; ww++) s += pl[gg][ww][h];
            float wv = 0.f;
            if (n < n1) wv = __expf(s + obs[h]);
            dp += wv;
            wsm[gg][h] = wv;
        }
        __syncthreads();

        // ---- phase 2: accumulate + copy out ----
#pragma unroll
        for (int j = 0; j < G; j++) {
            int n = nbase + j;
            if (n >= n1) break;
            float4 wA = *(const float4*)&wsm[j][0];
            float4 wB = *(const float4*)&wsm[j][4];
            float4 wC = *(const float4*)&wsm[j][8];
            float2 xv = *(const float2*)&xb[buf][j][c2];
            ua[0].x = fmaf(wA.x, xv.x, ua[0].x);  ua[0].y = fmaf(wA.x, xv.y, ua[0].y);
            ua[1].x = fmaf(wA.y, xv.x, ua[1].x);  ua[1].y = fmaf(wA.y, xv.y, ua[1].y);
            ua[2].x = fmaf(wA.z, xv.x, ua[2].x);  ua[2].y = fmaf(wA.z, xv.y, ua[2].y);
            ua[3].x = fmaf(wA.w, xv.x, ua[3].x);  ua[3].y = fmaf(wA.w, xv.y, ua[3].y);
            ua[4].x = fmaf(wB.x, xv.x, ua[4].x);  ua[4].y = fmaf(wB.x, xv.y, ua[4].y);
            ua[5].x = fmaf(wB.y, xv.x, ua[5].x);  ua[5].y = fmaf(wB.y, xv.y, ua[5].y);
            ua[6].x = fmaf(wB.z, xv.x, ua[6].x);  ua[6].y = fmaf(wB.z, xv.y, ua[6].y);
            ua[7].x = fmaf(wB.w, xv.x, ua[7].x);  ua[7].y = fmaf(wB.w, xv.y, ua[7].y);
            ua[8].x = fmaf(wC.x, xv.x, ua[8].x);  ua[8].y = fmaf(wC.x, xv.y, ua[8].y);
            ua[9].x = fmaf(wC.y, xv.x, ua[9].x);  ua[9].y = fmaf(wC.y, xv.y, ua[9].y);
            ua[10].x = fmaf(wC.z, xv.x, ua[10].x); ua[10].y = fmaf(wC.z, xv.y, ua[10].y);
            ua[11].x = fmaf(wC.w, xv.x, ua[11].x); ua[11].y = fmaf(wC.w, xv.y, ua[11].y);
            if (n > 0)
                *(float2*)&out[((size_t)b * Nt + n) * Cc + c2] = xv;
        }
        __syncthreads();
    }

    // store split partials
#pragma unroll
    for (int h = 0; h < 12; h++)
        *(float2*)&g_pu[sp][b][h][c2] = ua[h];
    if (tid < G * 12) dsm[tid] = dp;
    __syncthreads();
    if (tid < 12) {
        float s = 0.f;
#pragma unroll
        for (int gg = 0; gg < G; gg++) s += dsm[gg * 12 + tid];
        g_pd[sp][b][tid] = s;
    }
}

// ---------------- C1: cls partials (fused split-combine + normalize), 512 thr ----------------
__global__ void __launch_bounds__(512) k_cls(const float* __restrict__ qkv_w) {
    int h = blockIdx.x, kc = blockIdx.y;
    __shared__ float us[64][65];
    __shared__ float wv[64][65];
    __shared__ float dsh[64];
    int tid = threadIdx.x;
    if (tid < 64) {
        float s = 0.f;
#pragma unroll
        for (int sp = 0; sp < SPLITS; sp++) s += g_pd[sp][tid][h];
        dsh[tid] = 1.f / s;
    }
    __syncthreads();
#pragma unroll
    for (int rr = 0; rr < 2; rr++) {
        int i = tid + rr * 512;
        int r = i >> 4, c4 = (i & 15) * 4;
        float4 acc = make_float4(0.f, 0.f, 0.f, 0.f);
#pragma unroll
        for (int sp = 0; sp < SPLITS; sp++) {
            float4 p = *(const float4*)&g_pu[sp][r][h][kc * 64 + c4];
            acc.x += p.x; acc.y += p.y; acc.z += p.z; acc.w += p.w;
        }
        float inv = dsh[r];
        us[r][c4] = acc.x * inv; us[r][c4 + 1] = acc.y * inv;
        us[r][c4 + 2] = acc.z * inv; us[r][c4 + 3] = acc.w * inv;
        float4 wvv = *(const float4*)&qkv_w[(size_t)(2 * Cc + h * 64 + r) * Cc + kc * 64 + c4];
        wv[r][c4] = wvv.x; wv[r][c4 + 1] = wvv.y; wv[r][c4 + 2] = wvv.z; wv[r][c4 + 3] = wvv.w;
    }
    __syncthreads();
    int ty = tid >> 4, tx = tid & 15;
    float acc[2][4] = {};
#pragma unroll 8
    for (int c = 0; c < 64; c++) {
        float a0 = us[ty * 2 + 0][c], a1 = us[ty * 2 + 1][c];
        float b0 = wv[tx * 4 + 0][c], b1 = wv[tx * 4 + 1][c];
        float b2 = wv[tx * 4 + 2][c], b3 = wv[tx * 4 + 3][c];
        acc[0][0] += a0 * b0; acc[0][1] += a0 * b1; acc[0][2] += a0 * b2; acc[0][3] += a0 * b3;
        acc[1][0] += a1 * b0; acc[1][1] += a1 * b1; acc[1][2] += a1 * b2; acc[1][3] += a1 * b3;
    }
#pragma unroll
    for (int i = 0; i < 2; i++) {
        float4 v = make_float4(acc[i][0], acc[i][1], acc[i][2], acc[i][3]);
        *(float4*)&g_clsp[kc][ty * 2 + i][h * 64 + tx * 4] = v;
    }
}

// ---------------- C2: proj partials, 512 thr ----------------
__global__ void __launch_bounds__(512) k_proj(const float* __restrict__ qkv_b,
                                              const float* __restrict__ proj_w) {
    int jc = blockIdx.x, kc = blockIdx.y;
    __shared__ float cs[64][65];
    __shared__ float pw[64][65];
    int tid = threadIdx.x;
#pragma unroll
    for (int rr = 0; rr < 2; rr++) {
        int i = tid + rr * 512;
        int r = i >> 4, c4 = (i & 15) * 4;
        float4 s = *(const float4*)&qkv_b[2 * Cc + kc * 64 + c4];
#pragma unroll
        for (int p = 0; p < 12; p++) {
            float4 pv = *(const float4*)&g_clsp[p][r][kc * 64 + c4];
            s.x += pv.x; s.y += pv.y; s.z += pv.z; s.w += pv.w;
        }
        cs[r][c4] = s.x; cs[r][c4 + 1] = s.y; cs[r][c4 + 2] = s.z; cs[r][c4 + 3] = s.w;
        float4 wv = *(const float4*)&proj_w[(size_t)(jc * 64 + r) * Cc + kc * 64 + c4];
        pw[r][c4] = wv.x; pw[r][c4 + 1] = wv.y; pw[r][c4 + 2] = wv.z; pw[r][c4 + 3] = wv.w;
    }
    __syncthreads();
    int ty = tid >> 4, tx = tid & 15;
    float acc[2][4] = {};
#pragma unroll 8
    for (int c = 0; c < 64; c++) {
        float a0 = cs[ty * 2 + 0][c], a1 = cs[ty * 2 + 1][c];
        float b0 = pw[tx * 4 + 0][c], b1 = pw[tx * 4 + 1][c];
        float b2 = pw[tx * 4 + 2][c], b3 = pw[tx * 4 + 3][c];
        acc[0][0] += a0 * b0; acc[0][1] += a0 * b1; acc[0][2] += a0 * b2; acc[0][3] += a0 * b3;
        acc[1][0] += a1 * b0; acc[1][1] += a1 * b1; acc[1][2] += a1 * b2; acc[1][3] += a1 * b3;
    }
#pragma unroll
    for (int i = 0; i < 2; i++) {
        float4 v = make_float4(acc[i][0], acc[i][1], acc[i][2], acc[i][3]);
        *(float4*)&g_outp[kc][ty * 2 + i][jc * 64 + tx * 4] = v;
    }
}

// ---------------- C3: combine proj partials + proj_b -> out[:,0,:] ----------------
__global__ void k_final(const float* __restrict__ proj_b, float* __restrict__ out) {
    int idx = blockIdx.x * 256 + threadIdx.x;
    if (idx >= Bb * Cc / 4) return;
    int b = idx / 192, j4 = (idx % 192) * 4;
    float4 s = *(const float4*)&proj_b[j4];
#pragma unroll
    for (int p = 0; p < 12; p++) {
        float4 pv = *(const float4*)&g_outp[p][b][j4];
        s.x += pv.x; s.y += pv.y; s.z += pv.z; s.w += pv.w;
    }
    *(float4*)&out[(size_t)b * Nt * Cc + j4] = s;
}

// ---------------- launch ----------------
extern "C" void kernel_launch(void* const* d_in, const int* in_sizes, int n_in,
                              void* d_out, int out_size) {
    (void)in_sizes; (void)n_in; (void)out_size;
    const float* x      = (const float*)d_in[0];
    const float* qkv_w  = (const float*)d_in[1];
    const float* qkv_b  = (const float*)d_in[2];
    const float* proj_w = (const float*)d_in[3];
    const float* proj_b = (const float*)d_in[4];
    float* out = (float*)d_out;

    k_qpart<<<dim3(12, 12), 512>>>(x, qkv_w);
    k_t    <<<dim3(12, 12), 512>>>(qkv_w, qkv_b);
    k_attn <<<dim3(64, SPLITS), 384>>>(x, out);
    k_cls  <<<dim3(12, 12), 512>>>(qkv_w);
    k_proj <<<dim3(12, 12), 512>>>(qkv_b, proj_w);
    k_final<<<48, 256>>>(proj_b, out);
}